// round 14
// baseline (speedup 1.0000x reference)
#include <cuda_runtime.h>
#include <cuda_bf16.h>
#include <cstdint>

#define Bsz 64
#define Tsz 512
#define Isz 512
#define Hsz 512

// ---------------------------------------------------------------------------
// Static device scratch
// ---------------------------------------------------------------------------
// Wx pre-transposed: [dir][ctile(16)][hw(4)][qj(16)][kc(32)][8 cols]  (2 MB)
__device__ float g_wxt[2u * 512 * 512];

// 16 independent chain counters (8 btile x 2 dir), padded to 128B each
struct GCnt { unsigned v; unsigned pad[31]; };
__device__ GCnt g_gcount[16];

__global__ void reset_bar_kernel() {
    if (threadIdx.x < 16) g_gcount[threadIdx.x].v = 0;
}

// ---------------------------------------------------------------------------
// Wx transpose into the lane-contiguous chunked layout.
// g_wxt[dir][ctile][hw][qj][kc][cl] = Wx_dir[ctile*32+hw*8+cl][q*128+kc*4+j]
// ---------------------------------------------------------------------------
__global__ void __launch_bounds__(1024) wxt_kernel(
    const float* __restrict__ Wxf, const float* __restrict__ Wxb)
{
    const int idx = blockIdx.x * 1024 + threadIdx.x;   // 524288 total
    const int cl    = idx & 7;
    const int kc    = (idx >> 3) & 31;
    const int qj    = (idx >> 8) & 15;
    const int hw    = (idx >> 12) & 3;
    const int ctile = (idx >> 14) & 15;
    const int dir   = idx >> 18;
    const int q = qj >> 2, j = qj & 3;
    const int col = ctile * 32 + hw * 8 + cl;
    const int i   = q * 128 + kc * 4 + j;
    const float* W = dir ? Wxb : Wxf;
    g_wxt[idx] = W[col * Isz + i];
}

// ---------------------------------------------------------------------------
// Packed fp32x2 helpers (Blackwell FFMA2 path)
// ---------------------------------------------------------------------------
typedef unsigned long long ull;

__device__ __forceinline__ ull ffma2(ull a, ull b, ull c) {
    ull d;
    asm("fma.rn.f32x2 %0, %1, %2, %3;" : "=l"(d) : "l"(a), "l"(b), "l"(c));
    return d;
}
__device__ __forceinline__ ull pack2(float x) {
    ull d;
    asm("mov.b64 %0, {%1, %1};" : "=l"(d) : "f"(x));
    return d;
}
__device__ __forceinline__ float2 unpack2(ull a) {
    float2 r;
    asm("mov.b64 {%0, %1}, %2;" : "=f"(r.x), "=f"(r.y) : "l"(a));
    return r;
}

// ---------------------------------------------------------------------------
// Scoped sync primitives
// ---------------------------------------------------------------------------
__device__ __forceinline__ unsigned ld_acq_gpu(const unsigned* p) {
    unsigned v;
    asm volatile("ld.acquire.gpu.global.u32 %0, [%1];" : "=r"(v) : "l"(p) : "memory");
    return v;
}
__device__ __forceinline__ void red_rel_gpu(unsigned* p) {
    asm volatile("red.release.gpu.global.add.u32 [%0], 1;" :: "l"(p) : "memory");
}

// ---------------------------------------------------------------------------
// Fused persistent scan: xp-GEMM (chain-independent) + h-GEMM per step.
// 128 CTAs = 8 btile x 16 ctile; CTA owns 8 batches x 32 cols x 2 dirs.
// Warps 0-3 fwd, 4-7 bwd; each warp an independent chain agent (acquire
// poll / release arrive on its (btile,dir) counter, 64 arrivals/step).
//
// Per step per warp:
//   acc  = Wx-partials for t (x from L2, Wxt from L2; NO dependency)
//   poll counter (xp work has absorbed the wait)
//   acc += Wh-partials (h from y in L2, Wh from smem)
//   one butterfly -> 2 outputs/lane; tanh(v + xbias); store y; arrive.
//
// smem: WS[dir][kc][q*4+j][c], chunk stride 516 floats (odd 16B units).
// ---------------------------------------------------------------------------
#define SCAN_CTAS 128
#define WSZ (32 * 516)

__global__ void __launch_bounds__(256) scan_kernel(
    const float* __restrict__ x,
    const float* __restrict__ h0f, const float* __restrict__ h0b,
    const float* __restrict__ Whf, const float* __restrict__ Whb,
    const float* __restrict__ bxf, const float* __restrict__ bxb,
    float* __restrict__ y)
{
    extern __shared__ float sm[];

    const int cta   = blockIdx.x;
    const int btile = cta >> 4;
    const int ctile = cta & 15;
    const int b0    = btile << 3;   // 8 batches
    const int cbase = ctile << 5;   // 32 cols

    const int tid  = threadIdx.x;
    const int dir  = tid >> 7;      // 0 fwd (warps 0-3), 1 bwd (warps 4-7)
    const int htid = tid & 127;
    const int hw   = htid >> 5;     // warp within half
    const int lane = tid & 31;
    const int gidx = (btile << 1) | dir;

    const float* __restrict__ Wh = dir ? Whb : Whf;
    const float* __restrict__ h0 = dir ? h0b : h0f;
    const float* __restrict__ bx = dir ? bxb : bxf;

    float* WS = sm + dir * WSZ;

    // ---- load this dir's Wh slice once, permuted to the lane K-subsets ----
    // WS[kc][q*4+j][c] = Wh[cbase+c][q*128 + kc*4 + j]
    for (int i = htid; i < 32 * 128; i += 128) {
        int c  = i >> 7;
        int k4 = (i & 127) * 4;
        float4 v = *(const float4*)(Wh + (size_t)(cbase + c) * Hsz + k4);
        int q  = k4 >> 7;
        int kc = (k4 & 127) >> 2;
        float* p = WS + kc * 516 + (q * 4) * 32 + c;
        p[0 * 32] = v.x; p[1 * 32] = v.y; p[2 * 32] = v.z; p[3 * 32] = v.w;
    }
    __syncthreads();

    const int kc = lane;
    const int c0 = hw << 3;         // warp's 8 local cols

    // lane's 2 outputs after the halving butterfly (o = b_local*8 + c_local)
    const int o0 = ((lane & 1) << 5) | (((lane >> 1) & 1) << 4) |
                   (((lane >> 2) & 1) << 3) | (((lane >> 3) & 1) << 2) |
                   (((lane >> 4) & 1) << 1);
    const int b_out = b0 + (o0 >> 3);
    const int colg  = cbase + c0 + (o0 & 7);

    const float* wp = WS + kc * 516 + c0;
    // Wxt slice for this warp: [qj][kc][8]
    const float* wxbase = g_wxt + (((size_t)(dir * 16 + ctile) * 4 + hw) << 12)
                                + (kc << 3);
    // x base for this warp's lane: + t*Isz + b*(Tsz*Isz) + q*128
    const float* xlane = x + (size_t)b0 * Tsz * Isz + (kc << 2);

    const float2 xbias = make_float2(__ldg(bx + colg), __ldg(bx + colg + 1));

    unsigned* cnt = (unsigned*)&g_gcount[gidx].v;

    for (int step = 0; step < Tsz; step++) {
        const int t = dir ? (Tsz - 1 - step) : step;

        ull acc[8][4];
#pragma unroll
        for (int b = 0; b < 8; b++)
#pragma unroll
            for (int j = 0; j < 4; j++) acc[b][j] = 0ull;

        // ================= xp-GEMM: acc += Wx-part (NO chain dep) ==========
        {
            const float* xb = xlane + (size_t)t * Isz;
            float4 xq[8], xn[8];
#pragma unroll
            for (int b = 0; b < 8; b++)
                xq[b] = __ldcg((const float4*)(xb + (size_t)b * (Tsz * Isz)));

#pragma unroll
            for (int q = 0; q < 4; q++) {
                if (q < 3) {
#pragma unroll
                    for (int b = 0; b < 8; b++)
                        xn[b] = __ldcg((const float4*)(xb + (q + 1) * 128
                                                       + (size_t)b * (Tsz * Isz)));
                }
#pragma unroll
                for (int j = 0; j < 4; j++) {
                    const float* wr = wxbase + ((q * 4 + j) << 8);
                    ulonglong2 wa = *(const ulonglong2*)(wr);
                    ulonglong2 wb = *(const ulonglong2*)(wr + 4);
#pragma unroll
                    for (int b = 0; b < 8; b++) {
                        float xs = (j == 0) ? xq[b].x : (j == 1) ? xq[b].y
                                 : (j == 2) ? xq[b].z : xq[b].w;
                        ull xpk = pack2(xs);
                        acc[b][0] = ffma2(xpk, wa.x, acc[b][0]);
                        acc[b][1] = ffma2(xpk, wa.y, acc[b][1]);
                        acc[b][2] = ffma2(xpk, wb.x, acc[b][2]);
                        acc[b][3] = ffma2(xpk, wb.y, acc[b][3]);
                    }
                }
                if (q < 3) {
#pragma unroll
                    for (int b = 0; b < 8; b++) xq[b] = xn[b];
                }
            }
        }

        // ================= poll: previous step published? ==================
        if (step > 0) {
            const unsigned tgt = (unsigned)(step << 6);
            while (ld_acq_gpu(cnt) < tgt) { }
        }

        // ================= h-GEMM: acc += Wh-part ==========================
        {
            const float* hsrc;
            size_t rstride;
            if (step == 0) {
                hsrc = h0 + (size_t)b0 * Hsz; rstride = Hsz;
            } else {
                int tp = dir ? (t + 1) : (t - 1);
                hsrc = y + ((size_t)b0 * Tsz + tp) * (2 * Hsz) + ((size_t)dir << 9);
                rstride = (size_t)Tsz * 2 * Hsz;
            }
            const float* hbase = hsrc + (kc << 2);

            float4 hq[8], hn[8];
#pragma unroll
            for (int b = 0; b < 8; b++)
                hq[b] = __ldcg((const float4*)(hbase + b * rstride));

#pragma unroll
            for (int q = 0; q < 4; q++) {
                if (q < 3) {
#pragma unroll
                    for (int b = 0; b < 8; b++)
                        hn[b] = __ldcg((const float4*)(hbase + (q + 1) * 128 + b * rstride));
                }
#pragma unroll
                for (int j = 0; j < 4; j++) {
                    const float* wrow = wp + (q * 4 + j) * 32;
                    ulonglong2 wa = *(const ulonglong2*)(wrow);
                    ulonglong2 wb = *(const ulonglong2*)(wrow + 4);
#pragma unroll
                    for (int b = 0; b < 8; b++) {
                        float hs = (j == 0) ? hq[b].x : (j == 1) ? hq[b].y
                                 : (j == 2) ? hq[b].z : hq[b].w;
                        ull hpk = pack2(hs);
                        acc[b][0] = ffma2(hpk, wa.x, acc[b][0]);
                        acc[b][1] = ffma2(hpk, wa.y, acc[b][1]);
                        acc[b][2] = ffma2(hpk, wb.x, acc[b][2]);
                        acc[b][3] = ffma2(hpk, wb.y, acc[b][3]);
                    }
                }
                if (q < 3) {
#pragma unroll
                    for (int b = 0; b < 8; b++) hq[b] = hn[b];
                }
            }
        }

        // ---- unpack to 64 scalars (o = b*8 + c) ----
        float v[64];
#pragma unroll
        for (int b = 0; b < 8; b++)
#pragma unroll
            for (int cp = 0; cp < 4; cp++) {
                float2 u = unpack2(acc[b][cp]);
                v[b * 8 + cp * 2]     = u.x;
                v[b * 8 + cp * 2 + 1] = u.y;
            }

        // ---- 5-level jammed halving butterfly over the 32 kc lanes ----
        int n = 64;
#pragma unroll
        for (int m = 1; m < 32; m <<= 1) {
            n >>= 1;
            const bool hi = (lane & m) != 0;
#pragma unroll
            for (int i = 0; i < n; i++) {
                float send = hi ? v[i] : v[i + n];
                float keep = hi ? v[i + n] : v[i];
                v[i] = keep + __shfl_xor_sync(0xffffffffu, send, m);
            }
        }

        float r0 = tanhf(v[0] + xbias.x);
        float r1 = tanhf(v[1] + xbias.y);

        float* yp = y + ((size_t)b_out * Tsz + t) * (2 * Hsz) + (dir << 9) + colg;
        __stcg((float2*)yp, make_float2(r0, r1));

        // ---- warp arrive: syncwarp orders lane stores, lane0 publishes ----
        __syncwarp();
        if (lane == 0) red_rel_gpu(cnt);
    }
}

// ---------------------------------------------------------------------------
// Tail: hT_f = hs_f[T-1], hT_b = hs_b[t=0]
// ---------------------------------------------------------------------------
__global__ void tail_kernel(float* __restrict__ out)
{
    const int b = blockIdx.x;
    const int k = threadIdx.x;
    const float* y = out;
    const size_t yN = (size_t)Bsz * Tsz * 2 * Hsz;
    out[yN + (size_t)b * Hsz + k] =
        y[((size_t)b * Tsz + (Tsz - 1)) * (2 * Hsz) + k];
    out[yN + (size_t)Bsz * Hsz + (size_t)b * Hsz + k] =
        y[((size_t)b * Tsz) * (2 * Hsz) + Hsz + k];
}

// ---------------------------------------------------------------------------
extern "C" void kernel_launch(void* const* d_in, const int* in_sizes, int n_in,
                              void* d_out, int out_size)
{
    const float* x     = (const float*)d_in[0];
    const float* h0f   = (const float*)d_in[1];
    const float* h0b   = (const float*)d_in[2];
    const float* Wxf_w = (const float*)d_in[3];
    const float* Wxf_b = (const float*)d_in[4];
    const float* Whf_w = (const float*)d_in[5];
    const float* Wxb_w = (const float*)d_in[6];
    const float* Wxb_b = (const float*)d_in[7];
    const float* Whb_w = (const float*)d_in[8];
    float* out = (float*)d_out;

    const int scan_smem = (2 * WSZ) * (int)sizeof(float);  // 132096 B
    cudaFuncSetAttribute(scan_kernel,
                         cudaFuncAttributeMaxDynamicSharedMemorySize, scan_smem);

    reset_bar_kernel<<<1, 32>>>();
    wxt_kernel<<<512, 1024>>>(Wxf_w, Wxb_w);

    scan_kernel<<<SCAN_CTAS, 256, scan_smem>>>(
        x, h0f, h0b, Whf_w, Whb_w, Wxf_b, Wxb_b, out);

    tail_kernel<<<Bsz, Hsz>>>(out);
}